// round 14
// baseline (speedup 1.0000x reference)
#include <cuda_runtime.h>
#include <cuda_fp16.h>
#include <cstdint>
#include <cstddef>

// ---------------------------------------------------------------------------
// GemmRS: out[g,n] = sum_{s,k} A[s,g,k] * W[s,n,k]  == GEMM M=8192,N=1024,K=4096
// fp16 cast both operands (validated rel_err 2.9e-4 < 1e-3).
// GEMM: CTA 128x128, 8 warps 4(M)x2(N), warp tile 32x64, BK=64, 3-stage
// cp.async + syncthreads, occupancy 2. This configuration sits at the
// SMEM/tensor balance point (~2000 vs 2048 cyc per chunk-pair) -- the
// architectural floor for legacy mma.sync on sm_103a.
// Cast prepass: 2 rows per block (4608 blocks) to cut scheduling overhead.
// ---------------------------------------------------------------------------

#define MTOT 8192
#define NTOT 1024
#define KTOT 4096
#define NCHUNK 64              // KTOT / 64
#define BMT  128
#define BNT  128
#define STAGE_BYTES 32768      // A 16KB + B 16KB
#define NSTAGE 3

__device__ __half g_Ah[(size_t)MTOT * KTOT];   // 67 MB
__device__ __half g_Bh[(size_t)NTOT * KTOT];   // 8.4 MB

static __device__ __forceinline__ uint32_t smem_u32(const void* p) {
    uint32_t a;
    asm("{ .reg .u64 t; cvta.to.shared.u64 t, %1; cvt.u32.u64 %0, t; }"
        : "=r"(a) : "l"(p));
    return a;
}
static __device__ __forceinline__ void ldsm_x4(uint32_t& r0, uint32_t& r1,
                                               uint32_t& r2, uint32_t& r3,
                                               uint32_t addr) {
    asm volatile("ldmatrix.sync.aligned.m8n8.x4.shared.b16 {%0,%1,%2,%3}, [%4];"
                 : "=r"(r0), "=r"(r1), "=r"(r2), "=r"(r3) : "r"(addr));
}
static __device__ __forceinline__ void mma16816(float* c, const uint32_t* a,
                                                const uint32_t* b) {
    asm volatile(
        "mma.sync.aligned.m16n8k16.row.col.f32.f16.f16.f32 "
        "{%0,%1,%2,%3}, {%4,%5,%6,%7}, {%8,%9}, {%0,%1,%2,%3};"
        : "+f"(c[0]), "+f"(c[1]), "+f"(c[2]), "+f"(c[3])
        : "r"(a[0]), "r"(a[1]), "r"(a[2]), "r"(a[3]), "r"(b[0]), "r"(b[1]));
}

// ------------------------- fused cast prepass ------------------------------
// 4608 blocks, 2 rows each: blocks [0,4096) -> A rows 2b,2b+1;
// blocks [4096,4608) -> W rows 2(b-4096), 2(b-4096)+1. 256 thr x 16 floats/row.
__global__ __launch_bounds__(256) void cast_kernel(const float* __restrict__ A,
                                                   const float* __restrict__ W) {
    const int blk = blockIdx.x;
    const int t   = threadIdx.x;
    const int k0  = t << 4;
    const int s   = k0 >> 9;
    const int kl  = k0 & 511;

    const bool isA = (blk < (MTOT / 2));
    const int  r0  = isA ? (blk * 2) : ((blk - MTOT / 2) * 2);
    const int  rows_stride = isA ? MTOT : NTOT;
    const float* base = isA ? (A + (size_t)s * MTOT * 512 + kl)
                            : (W + (size_t)s * NTOT * 512 + kl);
    __half* dbase = (isA ? g_Ah : g_Bh);

#pragma unroll
    for (int r = 0; r < 2; ++r) {
        const int row = r0 + r;
        const float4* src = (const float4*)(base + (size_t)row * 512);
        float4 v0 = src[0], v1 = src[1], v2 = src[2], v3 = src[3];
        float x[16] = {v0.x,v0.y,v0.z,v0.w, v1.x,v1.y,v1.z,v1.w,
                       v2.x,v2.y,v2.z,v2.w, v3.x,v3.y,v3.z,v3.w};
        uint32_t h[8];
#pragma unroll
        for (int p = 0; p < 8; ++p) {
            __half h0 = __float2half_rn(x[2*p]);
            __half h1 = __float2half_rn(x[2*p+1]);
            h[p] = (uint32_t)__half_as_ushort(h0) |
                   ((uint32_t)__half_as_ushort(h1) << 16);
        }
        uint4* dst = (uint4*)(dbase + (size_t)row * KTOT + k0);
        dst[0] = make_uint4(h[0], h[1], h[2], h[3]);
        dst[1] = make_uint4(h[4], h[5], h[6], h[7]);
        (void)rows_stride;
    }
}

// ----------------------------- main GEMM ----------------------------------
__global__ __launch_bounds__(256, 2)
void gemm_mma_f16(float* __restrict__ C) {
    extern __shared__ char dsm[];
    const uint32_t sbase = smem_u32(dsm);

    const int tid  = threadIdx.x;
    const int wid  = tid >> 5;
    const int lane = tid & 31;
    const int wm   = wid & 3;
    const int wn   = wid >> 2;
    const int bm   = blockIdx.y * BMT;
    const int bn   = blockIdx.x * BNT;

    // cp.async mapping: thread -> 4 A rows + 4 B rows, 16B each
    const int rowi = tid >> 3;
    const int cg   = tid & 7;
    uint32_t a_off[4];
#pragma unroll
    for (int i = 0; i < 4; ++i) {
        uint32_t o = (uint32_t)(rowi + 32 * i) * 128u + (uint32_t)cg * 16u;
        a_off[i] = o ^ ((o >> 3) & 0x70u);
    }
    const __half* rowA = g_Ah + (size_t)(bm + rowi) * KTOT + cg * 8;
    const __half* rowB = g_Bh + (size_t)(bn + rowi) * KTOT + cg * 8;

    auto load_chunk = [&](int c, uint32_t st) {
        const uint32_t sb = sbase + st * STAGE_BYTES;
        const __half* pa = rowA + c * 64;
        const __half* pb = rowB + c * 64;
#pragma unroll
        for (int i = 0; i < 4; ++i)
            asm volatile("cp.async.cg.shared.global [%0], [%1], 16;"
                         :: "r"(sb + a_off[i]),
                            "l"(pa + (size_t)i * (32 * KTOT)) : "memory");
#pragma unroll
        for (int i = 0; i < 4; ++i)
            asm volatile("cp.async.cg.shared.global [%0], [%1], 16;"
                         :: "r"(sb + a_off[i] + 16384u),
                            "l"(pb + (size_t)i * (32 * KTOT)) : "memory");
        asm volatile("cp.async.commit_group;" ::: "memory");
    };

    // ldmatrix per-lane offsets (stage-relative)
    uint32_t a_rel[2], a_msk[2];
#pragma unroll
    for (int mt = 0; mt < 2; ++mt) {
        uint32_t m = wm * 32 + mt * 16 + (lane & 15);
        a_rel[mt] = m * 128u;
        a_msk[mt] = ((m & 7u) << 4) ^ ((uint32_t)(lane >> 4) * 16u);
    }
    uint32_t b_rel[4], b_msk[4];
#pragma unroll
    for (int np = 0; np < 4; ++np) {
        uint32_t n = wn * 64 + np * 16 + ((uint32_t)((lane >> 4) & 1) * 8u) + (lane & 7);
        b_rel[np] = 16384u + n * 128u;
        b_msk[np] = ((n & 7u) << 4) ^ ((uint32_t)((lane >> 3) & 1) * 16u);
    }

    float acc[2][8][4];
#pragma unroll
    for (int mt = 0; mt < 2; ++mt)
#pragma unroll
        for (int nt = 0; nt < 8; ++nt)
#pragma unroll
            for (int j = 0; j < 4; ++j) acc[mt][nt][j] = 0.f;

    load_chunk(0, 0);
    load_chunk(1, 1);

    uint32_t st_cur = 0, st_nxt = 2;

#pragma unroll 2
    for (int c = 0; c < NCHUNK; ++c) {
        if (c + 2 < NCHUNK) asm volatile("cp.async.wait_group 1;" ::: "memory");
        else                asm volatile("cp.async.wait_group 0;" ::: "memory");
        __syncthreads();
        if (c + 2 < NCHUNK) load_chunk(c + 2, st_nxt);

        const uint32_t stg = sbase + st_cur * STAGE_BYTES;
#pragma unroll
        for (int ks = 0; ks < 4; ++ks) {
            const uint32_t kb = (uint32_t)ks * 32u;
            uint32_t a[2][4], bfr[4][4];
#pragma unroll
            for (int mt = 0; mt < 2; ++mt)
                ldsm_x4(a[mt][0], a[mt][1], a[mt][2], a[mt][3],
                        stg + a_rel[mt] + (kb ^ a_msk[mt]));
#pragma unroll
            for (int np = 0; np < 4; ++np)
                ldsm_x4(bfr[np][0], bfr[np][1], bfr[np][2], bfr[np][3],
                        stg + b_rel[np] + (kb ^ b_msk[np]));
#pragma unroll
            for (int mt = 0; mt < 2; ++mt)
#pragma unroll
                for (int np = 0; np < 4; ++np) {
                    mma16816(acc[mt][np * 2 + 0], a[mt], &bfr[np][0]);
                    mma16816(acc[mt][np * 2 + 1], a[mt], &bfr[np][2]);
                }
        }
        st_cur = (st_cur == 2) ? 0 : st_cur + 1;
        st_nxt = (st_nxt == 2) ? 0 : st_nxt + 1;
    }

    // epilogue: direct float2 stores
#pragma unroll
    for (int mt = 0; mt < 2; ++mt) {
        const int row0 = bm + wm * 32 + mt * 16 + (lane >> 2);
#pragma unroll
        for (int nt = 0; nt < 8; ++nt) {
            const int col = bn + wn * 64 + nt * 8 + (lane & 3) * 2;
            float* c0 = C + (size_t)row0 * NTOT + col;
            float* c1 = c0 + 8 * NTOT;
            *(float2*)c0 = make_float2(acc[mt][nt][0], acc[mt][nt][1]);
            *(float2*)c1 = make_float2(acc[mt][nt][2], acc[mt][nt][3]);
        }
    }
}

// ----------------------------- launcher -----------------------------------
extern "C" void kernel_launch(void* const* d_in, const int* in_sizes, int n_in,
                              void* d_out, int out_size) {
    const float* A = (const float*)d_in[0];   // [8, 8192, 512]
    const float* W = (const float*)d_in[1];   // [8, 1024, 512]
    float* C = (float*)d_out;                 // [8192, 1024]
    (void)in_sizes; (void)n_in; (void)out_size;

    const int smem_bytes = NSTAGE * STAGE_BYTES;   // 96 KB
    static bool attr_done = false;                 // host-side config only
    if (!attr_done) {
        cudaFuncSetAttribute(gemm_mma_f16,
                             cudaFuncAttributeMaxDynamicSharedMemorySize, smem_bytes);
        attr_done = true;
    }

    cast_kernel<<<(MTOT + NTOT) / 2, 256>>>(A, W); // 4608 blocks, 2 rows each

    dim3 grid(NTOT / BNT, MTOT / BMT);             // (8, 64) = 512 CTAs
    gemm_mma_f16<<<grid, 256, smem_bytes>>>(C);
}

// round 15
// speedup vs baseline: 1.0059x; 1.0059x over previous
#include <cuda_runtime.h>
#include <cuda_fp16.h>
#include <cstdint>
#include <cstddef>

// ---------------------------------------------------------------------------
// GemmRS: out[g,n] = sum_{s,k} A[s,g,k] * W[s,n,k]  == GEMM M=8192,N=1024,K=4096
// fp16 cast both operands (validated rel_err 2.9e-4 < 1e-3).
// GEMM: CTA 128x128, 8 warps 4(M)x2(N), warp tile 32x64, BK=64, 3-stage
// cp.async + syncthreads, occupancy 2 (the measured floor configuration:
// SMEM/tensor balanced at ~2000 vs 2048 cyc per chunk-pair).
// Epilogue uses st.global.cs so C writes don't evict streamed A from L2.
// Cast prepass: R13 form (1 row per block; measured ~30us, near roofline).
// ---------------------------------------------------------------------------

#define MTOT 8192
#define NTOT 1024
#define KTOT 4096
#define NCHUNK 64              // KTOT / 64
#define BMT  128
#define BNT  128
#define STAGE_BYTES 32768      // A 16KB + B 16KB
#define NSTAGE 3

__device__ __half g_Ah[(size_t)MTOT * KTOT];   // 67 MB
__device__ __half g_Bh[(size_t)NTOT * KTOT];   // 8.4 MB

static __device__ __forceinline__ uint32_t smem_u32(const void* p) {
    uint32_t a;
    asm("{ .reg .u64 t; cvta.to.shared.u64 t, %1; cvt.u32.u64 %0, t; }"
        : "=r"(a) : "l"(p));
    return a;
}
static __device__ __forceinline__ void ldsm_x4(uint32_t& r0, uint32_t& r1,
                                               uint32_t& r2, uint32_t& r3,
                                               uint32_t addr) {
    asm volatile("ldmatrix.sync.aligned.m8n8.x4.shared.b16 {%0,%1,%2,%3}, [%4];"
                 : "=r"(r0), "=r"(r1), "=r"(r2), "=r"(r3) : "r"(addr));
}
static __device__ __forceinline__ void mma16816(float* c, const uint32_t* a,
                                                const uint32_t* b) {
    asm volatile(
        "mma.sync.aligned.m16n8k16.row.col.f32.f16.f16.f32 "
        "{%0,%1,%2,%3}, {%4,%5,%6,%7}, {%8,%9}, {%0,%1,%2,%3};"
        : "+f"(c[0]), "+f"(c[1]), "+f"(c[2]), "+f"(c[3])
        : "r"(a[0]), "r"(a[1]), "r"(a[2]), "r"(a[3]), "r"(b[0]), "r"(b[1]));
}
// streaming store: don't keep C lines in L2 (C is write-once, never re-read)
static __device__ __forceinline__ void stg_cs_v2(float* p, float x, float y) {
    asm volatile("st.global.cs.v2.f32 [%0], {%1, %2};"
                 :: "l"(p), "f"(x), "f"(y) : "memory");
}

// ------------------------- fused cast prepass (R13 form) -------------------
// Blocks [0,8192): A row m. Blocks [8192,9216): W row n. 256 thr x 16 floats.
__global__ __launch_bounds__(256) void cast_kernel(const float* __restrict__ A,
                                                   const float* __restrict__ W) {
    const int b = blockIdx.x;
    const int t = threadIdx.x;
    const int k0 = t << 4;
    const int s  = k0 >> 9;
    const int kl = k0 & 511;

    const bool isA = (b < MTOT);
    const int  row = isA ? b : (b - MTOT);
    const float4* src = isA ? (const float4*)(A + ((size_t)s * MTOT + row) * 512 + kl)
                            : (const float4*)(W + ((size_t)s * NTOT + row) * 512 + kl);
    float4 v0 = src[0], v1 = src[1], v2 = src[2], v3 = src[3];
    float x[16] = {v0.x,v0.y,v0.z,v0.w, v1.x,v1.y,v1.z,v1.w,
                   v2.x,v2.y,v2.z,v2.w, v3.x,v3.y,v3.z,v3.w};
    uint32_t h[8];
#pragma unroll
    for (int p = 0; p < 8; ++p) {
        __half h0 = __float2half_rn(x[2*p]);
        __half h1 = __float2half_rn(x[2*p+1]);
        h[p] = (uint32_t)__half_as_ushort(h0) |
               ((uint32_t)__half_as_ushort(h1) << 16);
    }
    uint4* dst = (uint4*)((isA ? g_Ah : g_Bh) + (size_t)row * KTOT + k0);
    dst[0] = make_uint4(h[0], h[1], h[2], h[3]);
    dst[1] = make_uint4(h[4], h[5], h[6], h[7]);
}

// ----------------------------- main GEMM ----------------------------------
__global__ __launch_bounds__(256, 2)
void gemm_mma_f16(float* __restrict__ C) {
    extern __shared__ char dsm[];
    const uint32_t sbase = smem_u32(dsm);

    const int tid  = threadIdx.x;
    const int wid  = tid >> 5;
    const int lane = tid & 31;
    const int wm   = wid & 3;
    const int wn   = wid >> 2;
    const int bm   = blockIdx.y * BMT;
    const int bn   = blockIdx.x * BNT;

    // cp.async mapping: thread -> 4 A rows + 4 B rows, 16B each
    const int rowi = tid >> 3;
    const int cg   = tid & 7;
    uint32_t a_off[4];
#pragma unroll
    for (int i = 0; i < 4; ++i) {
        uint32_t o = (uint32_t)(rowi + 32 * i) * 128u + (uint32_t)cg * 16u;
        a_off[i] = o ^ ((o >> 3) & 0x70u);
    }
    const __half* rowA = g_Ah + (size_t)(bm + rowi) * KTOT + cg * 8;
    const __half* rowB = g_Bh + (size_t)(bn + rowi) * KTOT + cg * 8;

    auto load_chunk = [&](int c, uint32_t st) {
        const uint32_t sb = sbase + st * STAGE_BYTES;
        const __half* pa = rowA + c * 64;
        const __half* pb = rowB + c * 64;
#pragma unroll
        for (int i = 0; i < 4; ++i)
            asm volatile("cp.async.cg.shared.global [%0], [%1], 16;"
                         :: "r"(sb + a_off[i]),
                            "l"(pa + (size_t)i * (32 * KTOT)) : "memory");
#pragma unroll
        for (int i = 0; i < 4; ++i)
            asm volatile("cp.async.cg.shared.global [%0], [%1], 16;"
                         :: "r"(sb + a_off[i] + 16384u),
                            "l"(pb + (size_t)i * (32 * KTOT)) : "memory");
        asm volatile("cp.async.commit_group;" ::: "memory");
    };

    // ldmatrix per-lane offsets (stage-relative)
    uint32_t a_rel[2], a_msk[2];
#pragma unroll
    for (int mt = 0; mt < 2; ++mt) {
        uint32_t m = wm * 32 + mt * 16 + (lane & 15);
        a_rel[mt] = m * 128u;
        a_msk[mt] = ((m & 7u) << 4) ^ ((uint32_t)(lane >> 4) * 16u);
    }
    uint32_t b_rel[4], b_msk[4];
#pragma unroll
    for (int np = 0; np < 4; ++np) {
        uint32_t n = wn * 64 + np * 16 + ((uint32_t)((lane >> 4) & 1) * 8u) + (lane & 7);
        b_rel[np] = 16384u + n * 128u;
        b_msk[np] = ((n & 7u) << 4) ^ ((uint32_t)((lane >> 3) & 1) * 16u);
    }

    float acc[2][8][4];
#pragma unroll
    for (int mt = 0; mt < 2; ++mt)
#pragma unroll
        for (int nt = 0; nt < 8; ++nt)
#pragma unroll
            for (int j = 0; j < 4; ++j) acc[mt][nt][j] = 0.f;

    load_chunk(0, 0);
    load_chunk(1, 1);

    uint32_t st_cur = 0, st_nxt = 2;

#pragma unroll 2
    for (int c = 0; c < NCHUNK; ++c) {
        if (c + 2 < NCHUNK) asm volatile("cp.async.wait_group 1;" ::: "memory");
        else                asm volatile("cp.async.wait_group 0;" ::: "memory");
        __syncthreads();
        if (c + 2 < NCHUNK) load_chunk(c + 2, st_nxt);

        const uint32_t stg = sbase + st_cur * STAGE_BYTES;
#pragma unroll
        for (int ks = 0; ks < 4; ++ks) {
            const uint32_t kb = (uint32_t)ks * 32u;
            uint32_t a[2][4], bfr[4][4];
#pragma unroll
            for (int mt = 0; mt < 2; ++mt)
                ldsm_x4(a[mt][0], a[mt][1], a[mt][2], a[mt][3],
                        stg + a_rel[mt] + (kb ^ a_msk[mt]));
#pragma unroll
            for (int np = 0; np < 4; ++np)
                ldsm_x4(bfr[np][0], bfr[np][1], bfr[np][2], bfr[np][3],
                        stg + b_rel[np] + (kb ^ b_msk[np]));
#pragma unroll
            for (int mt = 0; mt < 2; ++mt)
#pragma unroll
                for (int np = 0; np < 4; ++np) {
                    mma16816(acc[mt][np * 2 + 0], a[mt], &bfr[np][0]);
                    mma16816(acc[mt][np * 2 + 1], a[mt], &bfr[np][2]);
                }
        }
        st_cur = (st_cur == 2) ? 0 : st_cur + 1;
        st_nxt = (st_nxt == 2) ? 0 : st_nxt + 1;
    }

    // epilogue: streaming stores (C never re-read; keep L2 for A)
#pragma unroll
    for (int mt = 0; mt < 2; ++mt) {
        const int row0 = bm + wm * 32 + mt * 16 + (lane >> 2);
#pragma unroll
        for (int nt = 0; nt < 8; ++nt) {
            const int col = bn + wn * 64 + nt * 8 + (lane & 3) * 2;
            float* c0 = C + (size_t)row0 * NTOT + col;
            float* c1 = c0 + 8 * NTOT;
            stg_cs_v2(c0, acc[mt][nt][0], acc[mt][nt][1]);
            stg_cs_v2(c1, acc[mt][nt][2], acc[mt][nt][3]);
        }
    }
}

// ----------------------------- launcher -----------------------------------
extern "C" void kernel_launch(void* const* d_in, const int* in_sizes, int n_in,
                              void* d_out, int out_size) {
    const float* A = (const float*)d_in[0];   // [8, 8192, 512]
    const float* W = (const float*)d_in[1];   // [8, 1024, 512]
    float* C = (float*)d_out;                 // [8192, 1024]
    (void)in_sizes; (void)n_in; (void)out_size;

    const int smem_bytes = NSTAGE * STAGE_BYTES;   // 96 KB
    static bool attr_done = false;                 // host-side config only
    if (!attr_done) {
        cudaFuncSetAttribute(gemm_mma_f16,
                             cudaFuncAttributeMaxDynamicSharedMemorySize, smem_bytes);
        attr_done = true;
    }

    cast_kernel<<<MTOT + NTOT, 256>>>(A, W);       // 9216 blocks (R13 form)

    dim3 grid(NTOT / BNT, MTOT / BMT);             // (8, 64) = 512 CTAs
    gemm_mma_f16<<<grid, 256, smem_bytes>>>(C);
}

// round 16
// speedup vs baseline: 1.0130x; 1.0070x over previous
#include <cuda_runtime.h>
#include <cuda_fp16.h>
#include <cstdint>
#include <cstddef>

// ---------------------------------------------------------------------------
// GemmRS: out[g,n] = sum_{s,k} A[s,g,k] * W[s,n,k]  == GEMM M=8192,N=1024,K=4096
// fp16 cast both operands (validated rel_err 2.9e-4 < 1e-3 across 9 runs).
// GEMM: CTA 128x128, 8 warps 4(M)x2(N), warp tile 32x64, BK=64, 3-stage
// cp.async + syncthreads, occupancy 2. Measured floor for legacy mma.sync on
// sm_103a: SMEM crossbar and tensor pipe balanced at ~2048 cyc/chunk-pair
// (tensor 64%, GEMM 176us across R13/R14/R15). tcgen05 (the full-rate path)
// is blocked by the harness PTX target (compute_103, no 'a' features).
// This is the best measured configuration (R13: 209.4us total).
// ---------------------------------------------------------------------------

#define MTOT 8192
#define NTOT 1024
#define KTOT 4096
#define NCHUNK 64              // KTOT / 64
#define BMT  128
#define BNT  128
#define STAGE_BYTES 32768      // A 16KB + B 16KB
#define NSTAGE 3

__device__ __half g_Ah[(size_t)MTOT * KTOT];   // 67 MB
__device__ __half g_Bh[(size_t)NTOT * KTOT];   // 8.4 MB

static __device__ __forceinline__ uint32_t smem_u32(const void* p) {
    uint32_t a;
    asm("{ .reg .u64 t; cvta.to.shared.u64 t, %1; cvt.u32.u64 %0, t; }"
        : "=r"(a) : "l"(p));
    return a;
}
static __device__ __forceinline__ void ldsm_x4(uint32_t& r0, uint32_t& r1,
                                               uint32_t& r2, uint32_t& r3,
                                               uint32_t addr) {
    asm volatile("ldmatrix.sync.aligned.m8n8.x4.shared.b16 {%0,%1,%2,%3}, [%4];"
                 : "=r"(r0), "=r"(r1), "=r"(r2), "=r"(r3) : "r"(addr));
}
static __device__ __forceinline__ void mma16816(float* c, const uint32_t* a,
                                                const uint32_t* b) {
    asm volatile(
        "mma.sync.aligned.m16n8k16.row.col.f32.f16.f16.f32 "
        "{%0,%1,%2,%3}, {%4,%5,%6,%7}, {%8,%9}, {%0,%1,%2,%3};"
        : "+f"(c[0]), "+f"(c[1]), "+f"(c[2]), "+f"(c[3])
        : "r"(a[0]), "r"(a[1]), "r"(a[2]), "r"(a[3]), "r"(b[0]), "r"(b[1]));
}

// ------------------------- fused cast prepass ------------------------------
// Blocks [0,8192): A row m. Blocks [8192,9216): W row n. 256 thr x 16 floats.
__global__ __launch_bounds__(256) void cast_kernel(const float* __restrict__ A,
                                                   const float* __restrict__ W) {
    const int b = blockIdx.x;
    const int t = threadIdx.x;
    const int k0 = t << 4;
    const int s  = k0 >> 9;
    const int kl = k0 & 511;

    const bool isA = (b < MTOT);
    const int  row = isA ? b : (b - MTOT);
    const float4* src = isA ? (const float4*)(A + ((size_t)s * MTOT + row) * 512 + kl)
                            : (const float4*)(W + ((size_t)s * NTOT + row) * 512 + kl);
    float4 v0 = src[0], v1 = src[1], v2 = src[2], v3 = src[3];
    float x[16] = {v0.x,v0.y,v0.z,v0.w, v1.x,v1.y,v1.z,v1.w,
                   v2.x,v2.y,v2.z,v2.w, v3.x,v3.y,v3.z,v3.w};
    uint32_t h[8];
#pragma unroll
    for (int p = 0; p < 8; ++p) {
        __half h0 = __float2half_rn(x[2*p]);
        __half h1 = __float2half_rn(x[2*p+1]);
        h[p] = (uint32_t)__half_as_ushort(h0) |
               ((uint32_t)__half_as_ushort(h1) << 16);
    }
    uint4* dst = (uint4*)((isA ? g_Ah : g_Bh) + (size_t)row * KTOT + k0);
    dst[0] = make_uint4(h[0], h[1], h[2], h[3]);
    dst[1] = make_uint4(h[4], h[5], h[6], h[7]);
}

// ----------------------------- main GEMM ----------------------------------
__global__ __launch_bounds__(256, 2)
void gemm_mma_f16(float* __restrict__ C) {
    extern __shared__ char dsm[];
    const uint32_t sbase = smem_u32(dsm);

    const int tid  = threadIdx.x;
    const int wid  = tid >> 5;
    const int lane = tid & 31;
    const int wm   = wid & 3;
    const int wn   = wid >> 2;
    const int bm   = blockIdx.y * BMT;
    const int bn   = blockIdx.x * BNT;

    // cp.async mapping: thread -> 4 A rows + 4 B rows, 16B each
    const int rowi = tid >> 3;
    const int cg   = tid & 7;
    uint32_t a_off[4];
#pragma unroll
    for (int i = 0; i < 4; ++i) {
        uint32_t o = (uint32_t)(rowi + 32 * i) * 128u + (uint32_t)cg * 16u;
        a_off[i] = o ^ ((o >> 3) & 0x70u);
    }
    const __half* rowA = g_Ah + (size_t)(bm + rowi) * KTOT + cg * 8;
    const __half* rowB = g_Bh + (size_t)(bn + rowi) * KTOT + cg * 8;

    auto load_chunk = [&](int c, uint32_t st) {
        const uint32_t sb = sbase + st * STAGE_BYTES;
        const __half* pa = rowA + c * 64;
        const __half* pb = rowB + c * 64;
#pragma unroll
        for (int i = 0; i < 4; ++i)
            asm volatile("cp.async.cg.shared.global [%0], [%1], 16;"
                         :: "r"(sb + a_off[i]),
                            "l"(pa + (size_t)i * (32 * KTOT)) : "memory");
#pragma unroll
        for (int i = 0; i < 4; ++i)
            asm volatile("cp.async.cg.shared.global [%0], [%1], 16;"
                         :: "r"(sb + a_off[i] + 16384u),
                            "l"(pb + (size_t)i * (32 * KTOT)) : "memory");
        asm volatile("cp.async.commit_group;" ::: "memory");
    };

    // ldmatrix per-lane offsets (stage-relative)
    uint32_t a_rel[2], a_msk[2];
#pragma unroll
    for (int mt = 0; mt < 2; ++mt) {
        uint32_t m = wm * 32 + mt * 16 + (lane & 15);
        a_rel[mt] = m * 128u;
        a_msk[mt] = ((m & 7u) << 4) ^ ((uint32_t)(lane >> 4) * 16u);
    }
    uint32_t b_rel[4], b_msk[4];
#pragma unroll
    for (int np = 0; np < 4; ++np) {
        uint32_t n = wn * 64 + np * 16 + ((uint32_t)((lane >> 4) & 1) * 8u) + (lane & 7);
        b_rel[np] = 16384u + n * 128u;
        b_msk[np] = ((n & 7u) << 4) ^ ((uint32_t)((lane >> 3) & 1) * 16u);
    }

    float acc[2][8][4];
#pragma unroll
    for (int mt = 0; mt < 2; ++mt)
#pragma unroll
        for (int nt = 0; nt < 8; ++nt)
#pragma unroll
            for (int j = 0; j < 4; ++j) acc[mt][nt][j] = 0.f;

    load_chunk(0, 0);
    load_chunk(1, 1);

    uint32_t st_cur = 0, st_nxt = 2;

#pragma unroll 2
    for (int c = 0; c < NCHUNK; ++c) {
        if (c + 2 < NCHUNK) asm volatile("cp.async.wait_group 1;" ::: "memory");
        else                asm volatile("cp.async.wait_group 0;" ::: "memory");
        __syncthreads();
        if (c + 2 < NCHUNK) load_chunk(c + 2, st_nxt);

        const uint32_t stg = sbase + st_cur * STAGE_BYTES;
#pragma unroll
        for (int ks = 0; ks < 4; ++ks) {
            const uint32_t kb = (uint32_t)ks * 32u;
            uint32_t a[2][4], bfr[4][4];
#pragma unroll
            for (int mt = 0; mt < 2; ++mt)
                ldsm_x4(a[mt][0], a[mt][1], a[mt][2], a[mt][3],
                        stg + a_rel[mt] + (kb ^ a_msk[mt]));
#pragma unroll
            for (int np = 0; np < 4; ++np)
                ldsm_x4(bfr[np][0], bfr[np][1], bfr[np][2], bfr[np][3],
                        stg + b_rel[np] + (kb ^ b_msk[np]));
#pragma unroll
            for (int mt = 0; mt < 2; ++mt)
#pragma unroll
                for (int np = 0; np < 4; ++np) {
                    mma16816(acc[mt][np * 2 + 0], a[mt], &bfr[np][0]);
                    mma16816(acc[mt][np * 2 + 1], a[mt], &bfr[np][2]);
                }
        }
        st_cur = (st_cur == 2) ? 0 : st_cur + 1;
        st_nxt = (st_nxt == 2) ? 0 : st_nxt + 1;
    }

    // epilogue: direct float2 stores (plain stores measured best vs .cs)
#pragma unroll
    for (int mt = 0; mt < 2; ++mt) {
        const int row0 = bm + wm * 32 + mt * 16 + (lane >> 2);
#pragma unroll
        for (int nt = 0; nt < 8; ++nt) {
            const int col = bn + wn * 64 + nt * 8 + (lane & 3) * 2;
            float* c0 = C + (size_t)row0 * NTOT + col;
            float* c1 = c0 + 8 * NTOT;
            *(float2*)c0 = make_float2(acc[mt][nt][0], acc[mt][nt][1]);
            *(float2*)c1 = make_float2(acc[mt][nt][2], acc[mt][nt][3]);
        }
    }
}

// ----------------------------- launcher -----------------------------------
extern "C" void kernel_launch(void* const* d_in, const int* in_sizes, int n_in,
                              void* d_out, int out_size) {
    const float* A = (const float*)d_in[0];   // [8, 8192, 512]
    const float* W = (const float*)d_in[1];   // [8, 1024, 512]
    float* C = (float*)d_out;                 // [8192, 1024]
    (void)in_sizes; (void)n_in; (void)out_size;

    const int smem_bytes = NSTAGE * STAGE_BYTES;   // 96 KB
    static bool attr_done = false;                 // host-side config only
    if (!attr_done) {
        cudaFuncSetAttribute(gemm_mma_f16,
                             cudaFuncAttributeMaxDynamicSharedMemorySize, smem_bytes);
        attr_done = true;
    }

    cast_kernel<<<MTOT + NTOT, 256>>>(A, W);       // 9216 blocks

    dim3 grid(NTOT / BNT, MTOT / BMT);             // (8, 64) = 512 CTAs
    gemm_mma_f16<<<grid, 256, smem_bytes>>>(C);
}

// round 17
// speedup vs baseline: 1.0244x; 1.0113x over previous
#include <cuda_runtime.h>
#include <cuda_fp16.h>
#include <cstdint>
#include <cstddef>

// ---------------------------------------------------------------------------
// GemmRS: out[g,n] = sum_{s,k} A[s,g,k] * W[s,n,k]  == GEMM M=8192,N=1024,K=4096
// fp16 cast both operands (validated rel_err 2.9e-4 < 1e-3 across 10 runs).
// GEMM: CTA 128x128, 8 warps 4(M)x2(N), warp tile 32x64, BK=64, 3-stage
// cp.async + syncthreads, occupancy 2 — the measured floor for legacy
// mma.sync on sm_103a (SMEM crossbar and tensor pipe balanced at ~2048
// cyc/chunk-pair; tensor 64%, GEMM 176us across R13-R16).
// Only change vs best-measured R13: tail wait condition fixed from
// (c+2<NCHUNK) to (c+1<NCHUNK), removing a premature full-pipeline drain
// at the second-to-last chunk.
// ---------------------------------------------------------------------------

#define MTOT 8192
#define NTOT 1024
#define KTOT 4096
#define NCHUNK 64              // KTOT / 64
#define BMT  128
#define BNT  128
#define STAGE_BYTES 32768      // A 16KB + B 16KB
#define NSTAGE 3

__device__ __half g_Ah[(size_t)MTOT * KTOT];   // 67 MB
__device__ __half g_Bh[(size_t)NTOT * KTOT];   // 8.4 MB

static __device__ __forceinline__ uint32_t smem_u32(const void* p) {
    uint32_t a;
    asm("{ .reg .u64 t; cvta.to.shared.u64 t, %1; cvt.u32.u64 %0, t; }"
        : "=r"(a) : "l"(p));
    return a;
}
static __device__ __forceinline__ void ldsm_x4(uint32_t& r0, uint32_t& r1,
                                               uint32_t& r2, uint32_t& r3,
                                               uint32_t addr) {
    asm volatile("ldmatrix.sync.aligned.m8n8.x4.shared.b16 {%0,%1,%2,%3}, [%4];"
                 : "=r"(r0), "=r"(r1), "=r"(r2), "=r"(r3) : "r"(addr));
}
static __device__ __forceinline__ void mma16816(float* c, const uint32_t* a,
                                                const uint32_t* b) {
    asm volatile(
        "mma.sync.aligned.m16n8k16.row.col.f32.f16.f16.f32 "
        "{%0,%1,%2,%3}, {%4,%5,%6,%7}, {%8,%9}, {%0,%1,%2,%3};"
        : "+f"(c[0]), "+f"(c[1]), "+f"(c[2]), "+f"(c[3])
        : "r"(a[0]), "r"(a[1]), "r"(a[2]), "r"(a[3]), "r"(b[0]), "r"(b[1]));
}

// ------------------------- fused cast prepass ------------------------------
// Blocks [0,8192): A row m. Blocks [8192,9216): W row n. 256 thr x 16 floats.
__global__ __launch_bounds__(256) void cast_kernel(const float* __restrict__ A,
                                                   const float* __restrict__ W) {
    const int b = blockIdx.x;
    const int t = threadIdx.x;
    const int k0 = t << 4;
    const int s  = k0 >> 9;
    const int kl = k0 & 511;

    const bool isA = (b < MTOT);
    const int  row = isA ? b : (b - MTOT);
    const float4* src = isA ? (const float4*)(A + ((size_t)s * MTOT + row) * 512 + kl)
                            : (const float4*)(W + ((size_t)s * NTOT + row) * 512 + kl);
    float4 v0 = src[0], v1 = src[1], v2 = src[2], v3 = src[3];
    float x[16] = {v0.x,v0.y,v0.z,v0.w, v1.x,v1.y,v1.z,v1.w,
                   v2.x,v2.y,v2.z,v2.w, v3.x,v3.y,v3.z,v3.w};
    uint32_t h[8];
#pragma unroll
    for (int p = 0; p < 8; ++p) {
        __half h0 = __float2half_rn(x[2*p]);
        __half h1 = __float2half_rn(x[2*p+1]);
        h[p] = (uint32_t)__half_as_ushort(h0) |
               ((uint32_t)__half_as_ushort(h1) << 16);
    }
    uint4* dst = (uint4*)((isA ? g_Ah : g_Bh) + (size_t)row * KTOT + k0);
    dst[0] = make_uint4(h[0], h[1], h[2], h[3]);
    dst[1] = make_uint4(h[4], h[5], h[6], h[7]);
}

// ----------------------------- main GEMM ----------------------------------
__global__ __launch_bounds__(256, 2)
void gemm_mma_f16(float* __restrict__ C) {
    extern __shared__ char dsm[];
    const uint32_t sbase = smem_u32(dsm);

    const int tid  = threadIdx.x;
    const int wid  = tid >> 5;
    const int lane = tid & 31;
    const int wm   = wid & 3;
    const int wn   = wid >> 2;
    const int bm   = blockIdx.y * BMT;
    const int bn   = blockIdx.x * BNT;

    // cp.async mapping: thread -> 4 A rows + 4 B rows, 16B each
    const int rowi = tid >> 3;
    const int cg   = tid & 7;
    uint32_t a_off[4];
#pragma unroll
    for (int i = 0; i < 4; ++i) {
        uint32_t o = (uint32_t)(rowi + 32 * i) * 128u + (uint32_t)cg * 16u;
        a_off[i] = o ^ ((o >> 3) & 0x70u);
    }
    const __half* rowA = g_Ah + (size_t)(bm + rowi) * KTOT + cg * 8;
    const __half* rowB = g_Bh + (size_t)(bn + rowi) * KTOT + cg * 8;

    auto load_chunk = [&](int c, uint32_t st) {
        const uint32_t sb = sbase + st * STAGE_BYTES;
        const __half* pa = rowA + c * 64;
        const __half* pb = rowB + c * 64;
#pragma unroll
        for (int i = 0; i < 4; ++i)
            asm volatile("cp.async.cg.shared.global [%0], [%1], 16;"
                         :: "r"(sb + a_off[i]),
                            "l"(pa + (size_t)i * (32 * KTOT)) : "memory");
#pragma unroll
        for (int i = 0; i < 4; ++i)
            asm volatile("cp.async.cg.shared.global [%0], [%1], 16;"
                         :: "r"(sb + a_off[i] + 16384u),
                            "l"(pb + (size_t)i * (32 * KTOT)) : "memory");
        asm volatile("cp.async.commit_group;" ::: "memory");
    };

    // ldmatrix per-lane offsets (stage-relative)
    uint32_t a_rel[2], a_msk[2];
#pragma unroll
    for (int mt = 0; mt < 2; ++mt) {
        uint32_t m = wm * 32 + mt * 16 + (lane & 15);
        a_rel[mt] = m * 128u;
        a_msk[mt] = ((m & 7u) << 4) ^ ((uint32_t)(lane >> 4) * 16u);
    }
    uint32_t b_rel[4], b_msk[4];
#pragma unroll
    for (int np = 0; np < 4; ++np) {
        uint32_t n = wn * 64 + np * 16 + ((uint32_t)((lane >> 4) & 1) * 8u) + (lane & 7);
        b_rel[np] = 16384u + n * 128u;
        b_msk[np] = ((n & 7u) << 4) ^ ((uint32_t)((lane >> 3) & 1) * 16u);
    }

    float acc[2][8][4];
#pragma unroll
    for (int mt = 0; mt < 2; ++mt)
#pragma unroll
        for (int nt = 0; nt < 8; ++nt)
#pragma unroll
            for (int j = 0; j < 4; ++j) acc[mt][nt][j] = 0.f;

    load_chunk(0, 0);
    load_chunk(1, 1);

    uint32_t st_cur = 0, st_nxt = 2;

#pragma unroll 2
    for (int c = 0; c < NCHUNK; ++c) {
        // chunk c is complete when at most 1 newer group (chunk c+1) remains.
        // Only the very last chunk needs a full drain.
        if (c + 1 < NCHUNK) asm volatile("cp.async.wait_group 1;" ::: "memory");
        else                asm volatile("cp.async.wait_group 0;" ::: "memory");
        __syncthreads();
        if (c + 2 < NCHUNK) load_chunk(c + 2, st_nxt);

        const uint32_t stg = sbase + st_cur * STAGE_BYTES;
#pragma unroll
        for (int ks = 0; ks < 4; ++ks) {
            const uint32_t kb = (uint32_t)ks * 32u;
            uint32_t a[2][4], bfr[4][4];
#pragma unroll
            for (int mt = 0; mt < 2; ++mt)
                ldsm_x4(a[mt][0], a[mt][1], a[mt][2], a[mt][3],
                        stg + a_rel[mt] + (kb ^ a_msk[mt]));
#pragma unroll
            for (int np = 0; np < 4; ++np)
                ldsm_x4(bfr[np][0], bfr[np][1], bfr[np][2], bfr[np][3],
                        stg + b_rel[np] + (kb ^ b_msk[np]));
#pragma unroll
            for (int mt = 0; mt < 2; ++mt)
#pragma unroll
                for (int np = 0; np < 4; ++np) {
                    mma16816(acc[mt][np * 2 + 0], a[mt], &bfr[np][0]);
                    mma16816(acc[mt][np * 2 + 1], a[mt], &bfr[np][2]);
                }
        }
        st_cur = (st_cur == 2) ? 0 : st_cur + 1;
        st_nxt = (st_nxt == 2) ? 0 : st_nxt + 1;
    }

    // epilogue: direct float2 stores (plain stores measured best vs .cs)
#pragma unroll
    for (int mt = 0; mt < 2; ++mt) {
        const int row0 = bm + wm * 32 + mt * 16 + (lane >> 2);
#pragma unroll
        for (int nt = 0; nt < 8; ++nt) {
            const int col = bn + wn * 64 + nt * 8 + (lane & 3) * 2;
            float* c0 = C + (size_t)row0 * NTOT + col;
            float* c1 = c0 + 8 * NTOT;
            *(float2*)c0 = make_float2(acc[mt][nt][0], acc[mt][nt][1]);
            *(float2*)c1 = make_float2(acc[mt][nt][2], acc[mt][nt][3]);
        }
    }
}

// ----------------------------- launcher -----------------------------------
extern "C" void kernel_launch(void* const* d_in, const int* in_sizes, int n_in,
                              void* d_out, int out_size) {
    const float* A = (const float*)d_in[0];   // [8, 8192, 512]
    const float* W = (const float*)d_in[1];   // [8, 1024, 512]
    float* C = (float*)d_out;                 // [8192, 1024]
    (void)in_sizes; (void)n_in; (void)out_size;

    const int smem_bytes = NSTAGE * STAGE_BYTES;   // 96 KB
    static bool attr_done = false;                 // host-side config only
    if (!attr_done) {
        cudaFuncSetAttribute(gemm_mma_f16,
                             cudaFuncAttributeMaxDynamicSharedMemorySize, smem_bytes);
        attr_done = true;
    }

    cast_kernel<<<MTOT + NTOT, 256>>>(A, W);       // 9216 blocks

    dim3 grid(NTOT / BNT, MTOT / BMT);             // (8, 64) = 512 CTAs
    gemm_mma_f16<<<grid, 256, smem_bytes>>>(C);
}